// round 11
// baseline (speedup 1.0000x reference)
#include <cuda_runtime.h>
#include <cuda_bf16.h>

// ---------------- problem constants ----------------
#define LDIM 1024
#define CZ   128
#define CS   1024
#define KCAT 1280
#define ASTRIDE 136          // padded bf16 row stride
#define ZSTRIDE 132          // padded fp32 row stride for sZ
#define NSUB  19
#define NMBLK 8
#define GRID_MAIN (NSUB * NMBLK)   // 152

// ---------------- device scratch ----------------
__device__ __align__(16) float g_sc[LDIM * CZ];
__device__ __align__(16) float g_sr[LDIM * CZ];
__device__ float g_nc[LDIM];
__device__ float g_nr[LDIM];
__device__ float g_b1p[CZ];                                 // b1 + W1 @ ln_b
__device__ __align__(16) __nv_bfloat16 g_w1b[CZ * ASTRIDE]; // W1 * ln_g (bf16, padded)
__device__ __align__(16) float g_wct[(size_t)CS * KCAT];    // tf32-rounded wc
__device__ __align__(16) float g_cat[(size_t)LDIM * KCAT];  // tf32 [s_c|s_r|s_s_in]

// ---------------- helpers ----------------
__device__ __forceinline__ float to_tf32(float v) {
    float r; asm("cvt.rna.tf32.f32 %0, %1;" : "=f"(r) : "f"(v)); return r;
}
__device__ __forceinline__ void mma16816(float* d, const unsigned* a, const unsigned* b) {
    asm volatile(
        "mma.sync.aligned.m16n8k16.row.col.f32.bf16.bf16.f32 "
        "{%0,%1,%2,%3}, {%4,%5,%6,%7}, {%8,%9}, {%0,%1,%2,%3};\n"
        : "+f"(d[0]), "+f"(d[1]), "+f"(d[2]), "+f"(d[3])
        : "r"(a[0]), "r"(a[1]), "r"(a[2]), "r"(a[3]), "r"(b[0]), "r"(b[1]));
}
__device__ __forceinline__ void mma1688_tf32(float* d, const unsigned* a, const unsigned* b) {
    asm volatile(
        "mma.sync.aligned.m16n8k8.row.col.f32.tf32.tf32.f32 "
        "{%0,%1,%2,%3}, {%4,%5,%6,%7}, {%8,%9}, {%0,%1,%2,%3};\n"
        : "+f"(d[0]), "+f"(d[1]), "+f"(d[2]), "+f"(d[3])
        : "r"(a[0]), "r"(a[1]), "r"(a[2]), "r"(a[3]), "r"(b[0]), "r"(b[1]));
}
__device__ __forceinline__ void ldsm_x4(unsigned addr, unsigned& r0, unsigned& r1,
                                        unsigned& r2, unsigned& r3) {
    asm volatile("ldmatrix.sync.aligned.m8n8.x4.shared.b16 {%0,%1,%2,%3}, [%4];"
                 : "=r"(r0), "=r"(r1), "=r"(r2), "=r"(r3) : "r"(addr));
}
__device__ __forceinline__ void cp_async16(void* sptr, const void* gptr) {
    unsigned s = (unsigned)__cvta_generic_to_shared(sptr);
    asm volatile("cp.async.cg.shared.global [%0], [%1], 16;\n" :: "r"(s), "l"(gptr));
}

// ---------------- prep kernels ----------------
// blocks 0-127: row d of W1' = W1[d,:] * ln_g; block 128: b1' = b1 + W1 @ ln_b
__global__ void prep_w1b1(const float* __restrict__ w1, const float* __restrict__ b1,
                          const float* __restrict__ ln_g, const float* __restrict__ ln_b) {
    const int d = blockIdx.x, t = threadIdx.x;   // block 128
    if (d < CZ) {
        const float v = (t < CZ) ? w1[d * CZ + t] * ln_g[t] : 0.f;
        g_w1b[d * ASTRIDE + t] = __float2bfloat16(v);
        if (t < ASTRIDE - CZ) g_w1b[d * ASTRIDE + CZ + t] = __float2bfloat16(0.f);
    } else {
        // one thread per output d
        float acc = b1[t];
#pragma unroll 8
        for (int k = 0; k < CZ; ++k) acc += w1[t * CZ + k] * ln_b[k];
        g_b1p[t] = acc;
    }
}
__global__ void prep_wct(const float* __restrict__ wc) {
    int i = blockIdx.x * 256 + threadIdx.x;
    if (i < CS * KCAT) g_wct[i] = to_tf32(wc[i]);
}
__global__ void prep_catss(const float* __restrict__ s_s_in) {
    int i = blockIdx.x * 256 + threadIdx.x;
    if (i >= LDIM * CS) return;
    int l = i >> 10, k = i & 1023;
    g_cat[(size_t)l * KCAT + 256 + k] = to_tf32(s_s_in[i]);
}
// mask row sums -> g_nc; also zero g_sc/g_sr/g_nr
__global__ void norm_c(const float* __restrict__ mask) {
    const int l = blockIdx.x, t = threadIdx.x;  // block 256
    if (t < 128) g_sc[l * CZ + t] = 0.f;
    else         g_sr[l * CZ + (t - 128)] = 0.f;
    if (t == 0) g_nr[l] = 0.f;
    const float* p = mask + (size_t)l * LDIM;
    float s = 0.f;
#pragma unroll
    for (int i = 0; i < 4; ++i) s += p[t + i * 256];
#pragma unroll
    for (int o = 16; o; o >>= 1) s += __shfl_xor_sync(0xffffffffu, s, o);
    __shared__ float ws[8];
    if ((t & 31) == 0) ws[t >> 5] = s;
    __syncthreads();
    if (t == 0) {
        float tot = 0.f;
#pragma unroll
        for (int j = 0; j < 8; ++j) tot += ws[j];
        g_nc[l] = tot;
    }
}

// ---------------- main fused kernel (512 threads, 16 warps) ----------------
// smem: sZ 2*128*132*4=135168 | sA 34816 | sW1 34816 | sB1 512 | sMask3 1536 | sStat 1024
#define SMEM_MAIN (135168 + 34816 + 34816 + 512 + 1536 + 1024)

__global__ __launch_bounds__(512, 1)
void main_kernel(const float* __restrict__ s_z, const float* __restrict__ mask) {
    extern __shared__ __align__(16) char smem_raw[];
    float* sZ = (float*)smem_raw;                            // [2][128*132]
    __nv_bfloat16* sA  = (__nv_bfloat16*)(sZ + 2 * 128 * ZSTRIDE);
    __nv_bfloat16* sW1 = sA + CZ * ASTRIDE;
    float* sB1    = (float*)(sW1 + CZ * ASTRIDE);            // [128]
    float* sMask3 = sB1 + CZ;                                // [3][128]
    float2* sStat = (float2*)(sMask3 + 3 * CZ);              // [128] (rstd, -mu*rstd)

    const int tid = threadIdx.x, lane = tid & 31, wid = tid >> 5;
    const int wm = wid & 3, wn = wid >> 2;                   // 4x4 warp grid, 32x32 tiles
    const int cta = blockIdx.x;
    const int mblk = cta / NSUB, sub = cta % NSUB;
    const int l0 = (sub * LDIM) / NSUB, l1 = ((sub + 1) * LDIM) / NSUB;
    const int m0 = mblk * 128;

    for (int i = tid; i < CZ * ASTRIDE / 4; i += 512)
        ((uint2*)sW1)[i] = ((const uint2*)g_w1b)[i];
    if (tid < CZ) sB1[tid] = g_b1p[tid];
    __syncthreads();   // sW1/sB1 visible to all before hoists & GEMM

    // ldmatrix base addrs
    const unsigned sAb = (unsigned)__cvta_generic_to_shared(sA);
    const unsigned sWb = (unsigned)__cvta_generic_to_shared(sW1);
    const unsigned aRow = sAb + (unsigned)((wm * 32 + (lane & 15)) * (ASTRIDE * 2)) + ((lane >> 4) << 4);
    const unsigned bRow = sWb + (unsigned)((wn * 32 + (lane & 15)) * (ASTRIDE * 2)) + ((lane >> 4) << 4);

    // hoisted epilogue bias values (sB1 synced above)
    float2 bvv[4];
#pragma unroll
    for (int nt = 0; nt < 4; ++nt)
        bvv[nt] = *(const float2*)&sB1[wn * 32 + nt * 8 + (lane & 3) * 2];

    float sr_acc[2][4][4];
#pragma unroll
    for (int mt = 0; mt < 2; ++mt)
#pragma unroll
        for (int nt = 0; nt < 4; ++nt)
#pragma unroll
            for (int j = 0; j < 4; ++j) sr_acc[mt][nt][j] = 0.f;
    float nr_acc = 0.f;

    // prologue prefetch of l0 (slot 0, buffer 0)
    {
        const float* src = s_z + (((size_t)l0 * LDIM + m0) << 7);
        for (int i = tid; i < 4096; i += 512) {
            int row = i >> 5, seg = i & 31;
            cp_async16(sZ + row * ZSTRIDE + seg * 4, src + row * 128 + seg * 4);
        }
        if (tid < 32) cp_async16(sMask3 + tid * 4, mask + (size_t)l0 * LDIM + m0 + tid * 4);
        asm volatile("cp.async.commit_group;\n");
    }

    for (int l = l0; l < l1; ++l) {
        const int it = l - l0;
        const int buf = it & 1;
        const int mi = it % 3;
        if (l + 1 < l1) {
            const int nb = buf ^ 1, ni = (it + 1) % 3;
            const float* src = s_z + (((size_t)(l + 1) * LDIM + m0) << 7);
            float* dst = sZ + nb * 128 * ZSTRIDE;
            for (int i = tid; i < 4096; i += 512) {
                int row = i >> 5, seg = i & 31;
                cp_async16(dst + row * ZSTRIDE + seg * 4, src + row * 128 + seg * 4);
            }
            if (tid < 32) cp_async16(sMask3 + ni * CZ + tid * 4,
                                     mask + (size_t)(l + 1) * LDIM + m0 + tid * 4);
            asm volatile("cp.async.commit_group;\n");
            asm volatile("cp.async.wait_group 1;\n");
        } else {
            asm volatile("cp.async.wait_group 0;\n");
        }
        __syncthreads();   // A: buffer ready

        const float* zb = sZ + buf * 128 * ZSTRIDE;

        // ---- phase 1: row stats, 4 threads per row, 2 shuffle pairs ----
        {
            const int r = tid >> 2, h = tid & 3;
            const float4* base = (const float4*)(zb + r * ZSTRIDE + h * 32);
            float s = 0.f, q = 0.f;
#pragma unroll
            for (int i = 0; i < 8; ++i) {
                float4 x = base[i];
                s += x.x + x.y + x.z + x.w;
                q = fmaf(x.x, x.x, fmaf(x.y, x.y, fmaf(x.z, x.z, fmaf(x.w, x.w, q))));
            }
            s += __shfl_xor_sync(0xffffffffu, s, 1);
            q += __shfl_xor_sync(0xffffffffu, q, 1);
            s += __shfl_xor_sync(0xffffffffu, s, 2);
            q += __shfl_xor_sync(0xffffffffu, q, 2);
            if (h == 0) {
                const float mu = s * (1.f / 128.f);
                const float var = q * (1.f / 128.f) - mu * mu;
                const float rstd = rsqrtf(var + 1e-5f);
                sStat[r] = make_float2(rstd, -mu * rstd);
            }
        }
        __syncthreads();   // C: stats ready

        // ---- phase 2: normalize + bf16 pack (ln folded into W1'/b1') ----
#pragma unroll
        for (int j = 0; j < 8; ++j) {
            const int row = wid * 8 + j;
            const float2 st = sStat[row];
            float4 x = ((const float4*)(zb + row * ZSTRIDE))[lane];
            const float y0 = fmaf(x.x, st.x, st.y);
            const float y1 = fmaf(x.y, st.x, st.y);
            const float y2 = fmaf(x.z, st.x, st.y);
            const float y3 = fmaf(x.w, st.x, st.y);
            __nv_bfloat162 p0 = __floats2bfloat162_rn(y0, y1);
            __nv_bfloat162 p1 = __floats2bfloat162_rn(y2, y3);
            uint2 pk = make_uint2(*(unsigned*)&p0, *(unsigned*)&p1);
            *reinterpret_cast<uint2*>(sA + row * ASTRIDE + lane * 4) = pk;
        }
        __syncthreads();   // B: sA ready

        // mask values for epilogue + nr accumulation (from slot mi)
        const float* mks = sMask3 + mi * CZ;
        float mkv[2][2];
        mkv[0][0] = mks[wm * 32 + (lane >> 2)];
        mkv[0][1] = mks[wm * 32 + 8 + (lane >> 2)];
        mkv[1][0] = mks[wm * 32 + 16 + (lane >> 2)];
        mkv[1][1] = mks[wm * 32 + 24 + (lane >> 2)];
        if (tid < CZ) nr_acc += mks[tid];

        // ---- GEMM1: 32x32 warp tile over K=128 via ldmatrix ----
        float d1[2][4][4];
#pragma unroll
        for (int mt = 0; mt < 2; ++mt)
#pragma unroll
            for (int nt = 0; nt < 4; ++nt)
#pragma unroll
                for (int j = 0; j < 4; ++j) d1[mt][nt][j] = 0.f;
#pragma unroll
        for (int kk = 0; kk < 8; ++kk) {
            const unsigned colb = kk * 32;
            unsigned a[2][4], b[4][2];
            ldsm_x4(aRow + colb, a[0][0], a[0][1], a[0][2], a[0][3]);
            ldsm_x4(aRow + 16 * (ASTRIDE * 2) + colb, a[1][0], a[1][1], a[1][2], a[1][3]);
#pragma unroll
            for (int ntp = 0; ntp < 2; ++ntp) {
                unsigned q0, q1, q2, q3;
                ldsm_x4(bRow + ntp * 16 * (ASTRIDE * 2) + colb, q0, q1, q2, q3);
                b[2 * ntp][0] = q0; b[2 * ntp][1] = q2;
                b[2 * ntp + 1][0] = q1; b[2 * ntp + 1][1] = q3;
            }
#pragma unroll
            for (int mt = 0; mt < 2; ++mt)
#pragma unroll
                for (int nt = 0; nt < 4; ++nt) mma16816(d1[mt][nt], a[mt], b[nt]);
        }

        // ---- epilogue: relu(.+b1')*mask -> sr_acc (regs) + col sums (global RED) ----
        float cs[4][2];
#pragma unroll
        for (int nt = 0; nt < 4; ++nt) { cs[nt][0] = 0.f; cs[nt][1] = 0.f; }
#pragma unroll
        for (int nt = 0; nt < 4; ++nt) {
            const float bv0 = bvv[nt].x, bv1 = bvv[nt].y;
#pragma unroll
            for (int mt = 0; mt < 2; ++mt) {
                const float v0 = fmaxf(d1[mt][nt][0] + bv0, 0.f) * mkv[mt][0];
                const float v1 = fmaxf(d1[mt][nt][1] + bv1, 0.f) * mkv[mt][0];
                const float v2 = fmaxf(d1[mt][nt][2] + bv0, 0.f) * mkv[mt][1];
                const float v3 = fmaxf(d1[mt][nt][3] + bv1, 0.f) * mkv[mt][1];
                sr_acc[mt][nt][0] += v0; sr_acc[mt][nt][1] += v1;
                sr_acc[mt][nt][2] += v2; sr_acc[mt][nt][3] += v3;
                cs[nt][0] += v0 + v2;
                cs[nt][1] += v1 + v3;
            }
        }
#pragma unroll
        for (int nt = 0; nt < 4; ++nt) {
#pragma unroll
            for (int o = 4; o <= 16; o <<= 1) {
                cs[nt][0] += __shfl_xor_sync(0xffffffffu, cs[nt][0], o);
                cs[nt][1] += __shfl_xor_sync(0xffffffffu, cs[nt][1], o);
            }
        }
        if (lane < 4) {
            // 4 wm-warps share each column address; RED.F32 accumulates
#pragma unroll
            for (int nt = 0; nt < 4; ++nt) {
                const int c = wn * 32 + nt * 8 + lane * 2;
                atomicAdd(&g_sc[l * CZ + c], cs[nt][0]);
                atomicAdd(&g_sc[l * CZ + c + 1], cs[nt][1]);
            }
        }
    }

    // ---- flush per-m masked h sums + nr ----
#pragma unroll
    for (int mt = 0; mt < 2; ++mt)
#pragma unroll
        for (int nt = 0; nt < 4; ++nt) {
            const int r = wm * 32 + mt * 16 + (lane >> 2);
            const int c = wn * 32 + nt * 8 + (lane & 3) * 2;
            atomicAdd(&g_sr[(size_t)(m0 + r) * CZ + c],     sr_acc[mt][nt][0]);
            atomicAdd(&g_sr[(size_t)(m0 + r) * CZ + c + 1], sr_acc[mt][nt][1]);
            atomicAdd(&g_sr[(size_t)(m0 + r + 8) * CZ + c],     sr_acc[mt][nt][2]);
            atomicAdd(&g_sr[(size_t)(m0 + r + 8) * CZ + c + 1], sr_acc[mt][nt][3]);
        }
    if (tid < CZ) atomicAdd(&g_nr[m0 + tid], nr_acc);
}

// ---------------- finalize: s_c/s_r via W2, write cat cols 0..255 ----------------
#define SMEM_CATF (128 * 132 * 4 + 512 + 1024)

__global__ __launch_bounds__(256)
void cat_finalize(const float* __restrict__ w2, const float* __restrict__ b2) {
    extern __shared__ __align__(16) char cf_raw[];
    float* sw2 = (float*)cf_raw;          // [128][132]
    float* sb2 = sw2 + 128 * 132;
    float* sh  = sb2 + 128;               // [256]
    const int tid = threadIdx.x;

    for (int i = tid; i < 128 * 32; i += 256) {
        int r = i >> 5, kq = i & 31;
        ((float4*)(sw2 + r * 132))[kq] = ((const float4*)(w2 + r * 128))[kq];
    }
    if (tid < 128) sb2[tid] = b2[tid];
    __syncthreads();

    for (int li = 0; li < 16; ++li) {
        const int l = blockIdx.x * 16 + li;
        if (tid < 128) sh[tid] = g_sc[l * CZ + tid];
        else           sh[tid] = g_sr[l * CZ + (tid - 128)];
        __syncthreads();
        const int c = tid & 127;
        const float nraw = (tid < 128) ? g_nc[l] : g_nr[l];
        const float* hv = sh + (tid & 128);
        float acc = sb2[c] * nraw;
#pragma unroll 8
        for (int k = 0; k < 32; ++k) {
            float4 w = ((const float4*)(sw2 + c * 132))[k];
            float4 h = ((const float4*)hv)[k];
            acc += w.x * h.x + w.y * h.y + w.z * h.z + w.w * h.w;
        }
        g_cat[(size_t)l * KCAT + tid] = to_tf32(acc / fmaxf(nraw, 1.f));
        __syncthreads();
    }
}

// ---------------- final projection: [1024 x 1280] @ [1024 x 1280]^T in tf32 ----------------
#define SMEM_FG ((128 * 36 + 64 * 36) * 2 * 4)

__global__ __launch_bounds__(256, 2)
void final_gemm(const float* __restrict__ bc, float* __restrict__ out) {
    extern __shared__ __align__(16) float fg[];
    float* sAq = fg;                  // [2][128*36]
    float* sBq = fg + 2 * 128 * 36;   // [2][64*36]
    const int tid = threadIdx.x, lane = tid & 31, wid = tid >> 5;
    const int wm = wid >> 1, wn = wid & 1;
    const int lbase = blockIdx.y * 128, dbase = blockIdx.x * 64;
    const int NCH = KCAT / 32;   // 40

    float acc[2][4][4];
#pragma unroll
    for (int mt = 0; mt < 2; ++mt)
#pragma unroll
        for (int nt = 0; nt < 4; ++nt)
#pragma unroll
            for (int j = 0; j < 4; ++j) acc[mt][nt][j] = 0.f;

    {
        for (int i = tid; i < 1024; i += 256) {
            int row = i >> 3, seg = i & 7;
            cp_async16(sAq + row * 36 + seg * 4, g_cat + (size_t)(lbase + row) * KCAT + seg * 4);
        }
        for (int i = tid; i < 512; i += 256) {
            int row = i >> 3, seg = i & 7;
            cp_async16(sBq + row * 36 + seg * 4, g_wct + (size_t)(dbase + row) * KCAT + seg * 4);
        }
        asm volatile("cp.async.commit_group;\n");
    }

    for (int ch = 0; ch < NCH; ++ch) {
        const int buf = ch & 1;
        if (ch + 1 < NCH) {
            const int nb = buf ^ 1;
            const size_t kb = (size_t)(ch + 1) * 32;
            for (int i = tid; i < 1024; i += 256) {
                int row = i >> 3, seg = i & 7;
                cp_async16(sAq + nb * 128 * 36 + row * 36 + seg * 4,
                           g_cat + (size_t)(lbase + row) * KCAT + kb + seg * 4);
            }
            for (int i = tid; i < 512; i += 256) {
                int row = i >> 3, seg = i & 7;
                cp_async16(sBq + nb * 64 * 36 + row * 36 + seg * 4,
                           g_wct + (size_t)(dbase + row) * KCAT + kb + seg * 4);
            }
            asm volatile("cp.async.commit_group;\n");
            asm volatile("cp.async.wait_group 1;\n");
        } else {
            asm volatile("cp.async.wait_group 0;\n");
        }
        __syncthreads();

        const float* Ab = sAq + buf * 128 * 36;
        const float* Bb = sBq + buf * 64 * 36;
#pragma unroll
        for (int ks = 0; ks < 4; ++ks) {
            const int k0 = ks * 8 + (lane & 3);
            unsigned a[2][4], b[4][2];
#pragma unroll
            for (int mt = 0; mt < 2; ++mt) {
                const int r = wm * 32 + mt * 16 + (lane >> 2);
                a[mt][0] = __float_as_uint(Ab[r * 36 + k0]);
                a[mt][1] = __float_as_uint(Ab[(r + 8) * 36 + k0]);
                a[mt][2] = __float_as_uint(Ab[r * 36 + k0 + 4]);
                a[mt][3] = __float_as_uint(Ab[(r + 8) * 36 + k0 + 4]);
            }
#pragma unroll
            for (int nt = 0; nt < 4; ++nt) {
                const int n = wn * 32 + nt * 8 + (lane >> 2);
                b[nt][0] = __float_as_uint(Bb[n * 36 + k0]);
                b[nt][1] = __float_as_uint(Bb[n * 36 + k0 + 4]);
            }
#pragma unroll
            for (int mt = 0; mt < 2; ++mt)
#pragma unroll
                for (int nt = 0; nt < 4; ++nt) mma1688_tf32(acc[mt][nt], a[mt], b[nt]);
        }
        __syncthreads();
    }

#pragma unroll
    for (int mt = 0; mt < 2; ++mt)
#pragma unroll
        for (int nt = 0; nt < 4; ++nt) {
            const int r = wm * 32 + mt * 16 + (lane >> 2);
            const int c = wn * 32 + nt * 8 + (lane & 3) * 2;
            const int gr = lbase + r, gc = dbase + c;
            const float b0 = __ldg(&bc[gc]), b1v = __ldg(&bc[gc + 1]);
            out[(size_t)gr * CS + gc]           = acc[mt][nt][0] + b0;
            out[(size_t)gr * CS + gc + 1]       = acc[mt][nt][1] + b1v;
            out[(size_t)(gr + 8) * CS + gc]     = acc[mt][nt][2] + b0;
            out[(size_t)(gr + 8) * CS + gc + 1] = acc[mt][nt][3] + b1v;
        }
}

// ---------------- launcher ----------------
// Order chosen so main_kernel is the 4th launch (the slot ncu has been
// capturing every round). Dependencies preserved:
//   main      needs prep_w1b1 (W1'/b1') + norm_c (zeroed accs)
//   cat_finalize needs main + norm_c
//   final_gemm needs cat_finalize + prep_catss + prep_wct
extern "C" void kernel_launch(void* const* d_in, const int* in_sizes, int n_in,
                              void* d_out, int out_size) {
    const float* s_z    = (const float*)d_in[0];
    const float* s_s_in = (const float*)d_in[1];
    const float* mask   = (const float*)d_in[2];
    const float* ln_g   = (const float*)d_in[3];
    const float* ln_b   = (const float*)d_in[4];
    const float* w1     = (const float*)d_in[5];
    const float* b1     = (const float*)d_in[6];
    const float* w2     = (const float*)d_in[7];
    const float* b2     = (const float*)d_in[8];
    const float* wc     = (const float*)d_in[9];
    const float* bc     = (const float*)d_in[10];
    float* out = (float*)d_out;
    (void)in_sizes; (void)n_in; (void)out_size;

    cudaFuncSetAttribute(main_kernel, cudaFuncAttributeMaxDynamicSharedMemorySize, SMEM_MAIN);
    cudaFuncSetAttribute(cat_finalize, cudaFuncAttributeMaxDynamicSharedMemorySize, SMEM_CATF);
    cudaFuncSetAttribute(final_gemm, cudaFuncAttributeMaxDynamicSharedMemorySize, SMEM_FG);

    prep_w1b1<<<CZ + 1, 128>>>(w1, b1, ln_g, ln_b);
    norm_c<<<LDIM, 256>>>(mask);
    prep_wct<<<(CS * KCAT + 255) / 256, 256>>>(wc);
    main_kernel<<<GRID_MAIN, 512, SMEM_MAIN>>>(s_z, mask);
    prep_catss<<<(LDIM * CS + 255) / 256, 256>>>(s_s_in);
    cat_finalize<<<64, 256, SMEM_CATF>>>(w2, b2);
    final_gemm<<<dim3(16, 8), 256, SMEM_FG>>>(bc, out);
}

// round 12
// speedup vs baseline: 1.2143x; 1.2143x over previous
#include <cuda_runtime.h>
#include <cuda_bf16.h>

// ---------------- problem constants ----------------
#define LDIM 1024
#define CZ   128
#define CS   1024
#define KCAT 1280
#define ASTRIDE 136          // padded bf16 row stride (ldmatrix conflict-free)
#define ZROWS 36             // fp32 quarter-row stride (words)
#define ZBLK  4616           // floats per 32-ch quarter block (128*36 + 8 skew)
#define ZBUF  (4 * ZBLK)     // floats per full z buffer
#define NSUB  19
#define NMBLK 8
#define GRID_MAIN (NSUB * NMBLK)   // 152

// ---------------- device scratch ----------------
__device__ __align__(16) float g_sc[LDIM * CZ];
__device__ __align__(16) float g_sr[LDIM * CZ];
__device__ float g_nc[LDIM];
__device__ float g_nr[LDIM];
__device__ float g_b1p[CZ];                                 // b1 + W1 @ ln_b
__device__ __align__(16) __nv_bfloat16 g_w1b[CZ * ASTRIDE]; // W1 * ln_g (bf16, padded)
__device__ __align__(16) float g_wct[(size_t)CS * KCAT];    // tf32-rounded wc
__device__ __align__(16) float g_cat[(size_t)LDIM * KCAT];  // tf32 [s_c|s_r|s_s_in]

// ---------------- helpers ----------------
__device__ __forceinline__ float to_tf32(float v) {
    float r; asm("cvt.rna.tf32.f32 %0, %1;" : "=f"(r) : "f"(v)); return r;
}
__device__ __forceinline__ void mma16816(float* d, const unsigned* a, const unsigned* b) {
    asm volatile(
        "mma.sync.aligned.m16n8k16.row.col.f32.bf16.bf16.f32 "
        "{%0,%1,%2,%3}, {%4,%5,%6,%7}, {%8,%9}, {%0,%1,%2,%3};\n"
        : "+f"(d[0]), "+f"(d[1]), "+f"(d[2]), "+f"(d[3])
        : "r"(a[0]), "r"(a[1]), "r"(a[2]), "r"(a[3]), "r"(b[0]), "r"(b[1]));
}
__device__ __forceinline__ void mma1688_tf32(float* d, const unsigned* a, const unsigned* b) {
    asm volatile(
        "mma.sync.aligned.m16n8k8.row.col.f32.tf32.tf32.f32 "
        "{%0,%1,%2,%3}, {%4,%5,%6,%7}, {%8,%9}, {%0,%1,%2,%3};\n"
        : "+f"(d[0]), "+f"(d[1]), "+f"(d[2]), "+f"(d[3])
        : "r"(a[0]), "r"(a[1]), "r"(a[2]), "r"(a[3]), "r"(b[0]), "r"(b[1]));
}
__device__ __forceinline__ void ldsm_x4(unsigned addr, unsigned& r0, unsigned& r1,
                                        unsigned& r2, unsigned& r3) {
    asm volatile("ldmatrix.sync.aligned.m8n8.x4.shared.b16 {%0,%1,%2,%3}, [%4];"
                 : "=r"(r0), "=r"(r1), "=r"(r2), "=r"(r3) : "r"(addr));
}
__device__ __forceinline__ void cp_async16(void* sptr, const void* gptr) {
    unsigned s = (unsigned)__cvta_generic_to_shared(sptr);
    asm volatile("cp.async.cg.shared.global [%0], [%1], 16;\n" :: "r"(s), "l"(gptr));
}

// ---------------- prep kernels ----------------
__global__ void prep_w1b1(const float* __restrict__ w1, const float* __restrict__ b1,
                          const float* __restrict__ ln_g, const float* __restrict__ ln_b) {
    const int d = blockIdx.x, t = threadIdx.x;   // block 128
    if (d < CZ) {
        const float v = (t < CZ) ? w1[d * CZ + t] * ln_g[t] : 0.f;
        g_w1b[d * ASTRIDE + t] = __float2bfloat16(v);
        if (t < ASTRIDE - CZ) g_w1b[d * ASTRIDE + CZ + t] = __float2bfloat16(0.f);
    } else {
        float acc = b1[t];
#pragma unroll 8
        for (int k = 0; k < CZ; ++k) acc += w1[t * CZ + k] * ln_b[k];
        g_b1p[t] = acc;
    }
}
__global__ void prep_wct(const float* __restrict__ wc) {
    int i = blockIdx.x * 256 + threadIdx.x;
    if (i < CS * KCAT) g_wct[i] = to_tf32(wc[i]);
}
__global__ void prep_catss(const float* __restrict__ s_s_in) {
    int i = blockIdx.x * 256 + threadIdx.x;
    if (i >= LDIM * CS) return;
    int l = i >> 10, k = i & 1023;
    g_cat[(size_t)l * KCAT + 256 + k] = to_tf32(s_s_in[i]);
}
// mask row sums -> g_nc; also zero g_sc/g_sr/g_nr
__global__ void norm_c(const float* __restrict__ mask) {
    const int l = blockIdx.x, t = threadIdx.x;  // block 256
    if (t < 128) g_sc[l * CZ + t] = 0.f;
    else         g_sr[l * CZ + (t - 128)] = 0.f;
    if (t == 0) g_nr[l] = 0.f;
    const float* p = mask + (size_t)l * LDIM;
    float s = 0.f;
#pragma unroll
    for (int i = 0; i < 4; ++i) s += p[t + i * 256];
#pragma unroll
    for (int o = 16; o; o >>= 1) s += __shfl_xor_sync(0xffffffffu, s, o);
    __shared__ float ws[8];
    if ((t & 31) == 0) ws[t >> 5] = s;
    __syncthreads();
    if (t == 0) {
        float tot = 0.f;
#pragma unroll
        for (int j = 0; j < 8; ++j) tot += ws[j];
        g_nc[l] = tot;
    }
}

// ---------------- main fused kernel (512 threads, 16 warps) ----------------
// smem: sZ 2*ZBUF*4 = 147712 | sA 34816 | sW1 34816 | sB1 512 | sMask3 1536 = 219392
#define SMEM_MAIN (2 * ZBUF * 4 + 34816 + 34816 + 512 + 1536)

__global__ __launch_bounds__(512, 1)
void main_kernel(const float* __restrict__ s_z, const float* __restrict__ mask) {
    extern __shared__ __align__(16) float smemf[];
    float* sZ = smemf;                                        // [2][ZBUF] quarter-split
    __nv_bfloat16* sA  = (__nv_bfloat16*)(sZ + 2 * ZBUF);     // [128][136]
    __nv_bfloat16* sW1 = sA + CZ * ASTRIDE;                   // [128][136]
    float* sB1    = (float*)(sW1 + CZ * ASTRIDE);             // [128]
    float* sMask3 = sB1 + CZ;                                 // [3][128]

    const int tid = threadIdx.x, lane = tid & 31, wid = tid >> 5;
    const int wm = wid & 3, wn = wid >> 2;                    // 4x4 warp grid, 32x32 tiles
    const int cta = blockIdx.x;
    const int mblk = cta / NSUB, sub = cta % NSUB;
    const int l0 = (sub * LDIM) / NSUB, l1 = ((sub + 1) * LDIM) / NSUB;
    const int m0 = mblk * 128;

    for (int i = tid; i < CZ * ASTRIDE / 4; i += 512)
        ((uint2*)sW1)[i] = ((const uint2*)g_w1b)[i];
    if (tid < CZ) sB1[tid] = g_b1p[tid];
    __syncthreads();   // sW1/sB1 visible before hoists & GEMM

    // LN mapping: row rr, quarter pp (permuted for conflict-free banks: 8p+4r)
    const int rr = tid >> 2, qq = tid & 3, pp = (qq + rr) & 3;

    // ldmatrix base addrs
    const unsigned sAb = (unsigned)__cvta_generic_to_shared(sA);
    const unsigned sWb = (unsigned)__cvta_generic_to_shared(sW1);
    const unsigned aRow = sAb + (unsigned)((wm * 32 + (lane & 15)) * (ASTRIDE * 2)) + ((lane >> 4) << 4);
    const unsigned bRow = sWb + (unsigned)((wn * 32 + (lane & 15)) * (ASTRIDE * 2)) + ((lane >> 4) << 4);

    // hoisted epilogue bias values (sB1 synced above)
    float2 bvv[4];
#pragma unroll
    for (int nt = 0; nt < 4; ++nt)
        bvv[nt] = *(const float2*)&sB1[wn * 32 + nt * 8 + (lane & 3) * 2];

    float sr_acc[2][4][4];
#pragma unroll
    for (int mt = 0; mt < 2; ++mt)
#pragma unroll
        for (int nt = 0; nt < 4; ++nt)
#pragma unroll
            for (int j = 0; j < 4; ++j) sr_acc[mt][nt][j] = 0.f;
    float nr_acc = 0.f;

    // prologue prefetch of l0 (buffer 0, mask slot 0)
    {
        const float* src = s_z + (((size_t)l0 * LDIM + m0) << 7);
        for (int i = tid; i < 4096; i += 512) {
            int m = i >> 5, j = i & 31;          // j = 16B chunk within row
            cp_async16(sZ + (j >> 3) * ZBLK + m * ZROWS + (j & 7) * 4, src + (size_t)i * 4);
        }
        if (tid < 32) cp_async16(sMask3 + tid * 4, mask + (size_t)l0 * LDIM + m0 + tid * 4);
        asm volatile("cp.async.commit_group;\n");
    }

    for (int l = l0; l < l1; ++l) {
        const int it = l - l0;
        const int buf = it & 1;
        const int mi = it % 3;
        if (l + 1 < l1) {
            const float* src = s_z + (((size_t)(l + 1) * LDIM + m0) << 7);
            float* dst = sZ + (buf ^ 1) * ZBUF;
            for (int i = tid; i < 4096; i += 512) {
                int m = i >> 5, j = i & 31;
                cp_async16(dst + (j >> 3) * ZBLK + m * ZROWS + (j & 7) * 4, src + (size_t)i * 4);
            }
            if (tid < 32) cp_async16(sMask3 + ((it + 1) % 3) * CZ + tid * 4,
                                     mask + (size_t)(l + 1) * LDIM + m0 + tid * 4);
            asm volatile("cp.async.commit_group;\n");
            asm volatile("cp.async.wait_group 1;\n");
        } else {
            asm volatile("cp.async.wait_group 0;\n");
        }
        __syncthreads();   // A: z buffer + mask ready

        // ---- single-pass register LN (thread: row rr, quarter pp; 4 shuffles) ----
        {
            const float4* zb = (const float4*)(sZ + buf * ZBUF + pp * ZBLK + rr * ZROWS);
            float4 x[8];
#pragma unroll
            for (int i = 0; i < 8; ++i) x[i] = zb[i];
            float s = 0.f, q = 0.f;
#pragma unroll
            for (int i = 0; i < 8; ++i) {
                s += (x[i].x + x[i].y) + (x[i].z + x[i].w);
                q = fmaf(x[i].x, x[i].x, fmaf(x[i].y, x[i].y,
                    fmaf(x[i].z, x[i].z, fmaf(x[i].w, x[i].w, q))));
            }
            s += __shfl_xor_sync(0xffffffffu, s, 1);
            q += __shfl_xor_sync(0xffffffffu, q, 1);
            s += __shfl_xor_sync(0xffffffffu, s, 2);
            q += __shfl_xor_sync(0xffffffffu, q, 2);
            const float mu = s * (1.f / 128.f);
            const float var = q * (1.f / 128.f) - mu * mu;
            const float rstd = rsqrtf(var + 1e-5f);
            const float nb = -mu * rstd;
            uint4* dstA = (uint4*)(sA + rr * ASTRIDE + pp * 32);
#pragma unroll
            for (int i = 0; i < 4; ++i) {
                const float4 u = x[2 * i], v = x[2 * i + 1];
                __nv_bfloat162 p0 = __floats2bfloat162_rn(fmaf(u.x, rstd, nb), fmaf(u.y, rstd, nb));
                __nv_bfloat162 p1 = __floats2bfloat162_rn(fmaf(u.z, rstd, nb), fmaf(u.w, rstd, nb));
                __nv_bfloat162 p2 = __floats2bfloat162_rn(fmaf(v.x, rstd, nb), fmaf(v.y, rstd, nb));
                __nv_bfloat162 p3 = __floats2bfloat162_rn(fmaf(v.z, rstd, nb), fmaf(v.w, rstd, nb));
                dstA[i] = make_uint4(*(unsigned*)&p0, *(unsigned*)&p1,
                                     *(unsigned*)&p2, *(unsigned*)&p3);
            }
        }
        __syncthreads();   // B: sA ready

        // mask values for epilogue + nr accumulation (slot mi)
        const float* mks = sMask3 + mi * CZ;
        float mkv[2][2];
        mkv[0][0] = mks[wm * 32 + (lane >> 2)];
        mkv[0][1] = mks[wm * 32 + 8 + (lane >> 2)];
        mkv[1][0] = mks[wm * 32 + 16 + (lane >> 2)];
        mkv[1][1] = mks[wm * 32 + 24 + (lane >> 2)];
        if (tid < CZ) nr_acc += mks[tid];

        // ---- GEMM1: 32x32 warp tile over K=128 via ldmatrix ----
        float d1[2][4][4];
#pragma unroll
        for (int mt = 0; mt < 2; ++mt)
#pragma unroll
            for (int nt = 0; nt < 4; ++nt)
#pragma unroll
                for (int j = 0; j < 4; ++j) d1[mt][nt][j] = 0.f;
#pragma unroll
        for (int kk = 0; kk < 8; ++kk) {
            const unsigned colb = kk * 32;
            unsigned a[2][4], b[4][2];
            ldsm_x4(aRow + colb, a[0][0], a[0][1], a[0][2], a[0][3]);
            ldsm_x4(aRow + 16 * (ASTRIDE * 2) + colb, a[1][0], a[1][1], a[1][2], a[1][3]);
#pragma unroll
            for (int ntp = 0; ntp < 2; ++ntp) {
                unsigned q0, q1, q2, q3;
                ldsm_x4(bRow + ntp * 16 * (ASTRIDE * 2) + colb, q0, q1, q2, q3);
                b[2 * ntp][0] = q0; b[2 * ntp][1] = q2;
                b[2 * ntp + 1][0] = q1; b[2 * ntp + 1][1] = q3;
            }
#pragma unroll
            for (int mt = 0; mt < 2; ++mt)
#pragma unroll
                for (int nt = 0; nt < 4; ++nt) mma16816(d1[mt][nt], a[mt], b[nt]);
        }

        // ---- epilogue: relu(.+b1')*mask -> sr_acc (regs) + col sums (global RED) ----
        float cs[4][2];
#pragma unroll
        for (int nt = 0; nt < 4; ++nt) { cs[nt][0] = 0.f; cs[nt][1] = 0.f; }
#pragma unroll
        for (int nt = 0; nt < 4; ++nt) {
            const float bv0 = bvv[nt].x, bv1 = bvv[nt].y;
#pragma unroll
            for (int mt = 0; mt < 2; ++mt) {
                const float v0 = fmaxf(d1[mt][nt][0] + bv0, 0.f) * mkv[mt][0];
                const float v1 = fmaxf(d1[mt][nt][1] + bv1, 0.f) * mkv[mt][0];
                const float v2 = fmaxf(d1[mt][nt][2] + bv0, 0.f) * mkv[mt][1];
                const float v3 = fmaxf(d1[mt][nt][3] + bv1, 0.f) * mkv[mt][1];
                sr_acc[mt][nt][0] += v0; sr_acc[mt][nt][1] += v1;
                sr_acc[mt][nt][2] += v2; sr_acc[mt][nt][3] += v3;
                cs[nt][0] += v0 + v2;
                cs[nt][1] += v1 + v3;
            }
        }
#pragma unroll
        for (int nt = 0; nt < 4; ++nt) {
#pragma unroll
            for (int o = 4; o <= 16; o <<= 1) {
                cs[nt][0] += __shfl_xor_sync(0xffffffffu, cs[nt][0], o);
                cs[nt][1] += __shfl_xor_sync(0xffffffffu, cs[nt][1], o);
            }
        }
        if (lane < 4) {
#pragma unroll
            for (int nt = 0; nt < 4; ++nt) {
                const int c = wn * 32 + nt * 8 + lane * 2;
                atomicAdd(&g_sc[l * CZ + c], cs[nt][0]);
                atomicAdd(&g_sc[l * CZ + c + 1], cs[nt][1]);
            }
        }
    }

    // ---- flush per-m masked h sums + nr ----
#pragma unroll
    for (int mt = 0; mt < 2; ++mt)
#pragma unroll
        for (int nt = 0; nt < 4; ++nt) {
            const int r = wm * 32 + mt * 16 + (lane >> 2);
            const int c = wn * 32 + nt * 8 + (lane & 3) * 2;
            atomicAdd(&g_sr[(size_t)(m0 + r) * CZ + c],     sr_acc[mt][nt][0]);
            atomicAdd(&g_sr[(size_t)(m0 + r) * CZ + c + 1], sr_acc[mt][nt][1]);
            atomicAdd(&g_sr[(size_t)(m0 + r + 8) * CZ + c],     sr_acc[mt][nt][2]);
            atomicAdd(&g_sr[(size_t)(m0 + r + 8) * CZ + c + 1], sr_acc[mt][nt][3]);
        }
    if (tid < CZ) atomicAdd(&g_nr[m0 + tid], nr_acc);
}

// ---------------- finalize: s_c/s_r via W2, write cat cols 0..255 ----------------
#define SMEM_CATF (128 * 132 * 4 + 512 + 1024)

__global__ __launch_bounds__(256)
void cat_finalize(const float* __restrict__ w2, const float* __restrict__ b2) {
    extern __shared__ __align__(16) char cf_raw[];
    float* sw2 = (float*)cf_raw;          // [128][132]
    float* sb2 = sw2 + 128 * 132;
    float* sh  = sb2 + 128;               // [256]
    const int tid = threadIdx.x;

    for (int i = tid; i < 128 * 32; i += 256) {
        int r = i >> 5, kq = i & 31;
        ((float4*)(sw2 + r * 132))[kq] = ((const float4*)(w2 + r * 128))[kq];
    }
    if (tid < 128) sb2[tid] = b2[tid];
    __syncthreads();

    for (int li = 0; li < 16; ++li) {
        const int l = blockIdx.x * 16 + li;
        if (tid < 128) sh[tid] = g_sc[l * CZ + tid];
        else           sh[tid] = g_sr[l * CZ + (tid - 128)];
        __syncthreads();
        const int c = tid & 127;
        const float nraw = (tid < 128) ? g_nc[l] : g_nr[l];
        const float* hv = sh + (tid & 128);
        float acc = sb2[c] * nraw;
#pragma unroll 8
        for (int k = 0; k < 32; ++k) {
            float4 w = ((const float4*)(sw2 + c * 132))[k];
            float4 h = ((const float4*)hv)[k];
            acc += w.x * h.x + w.y * h.y + w.z * h.z + w.w * h.w;
        }
        g_cat[(size_t)l * KCAT + tid] = to_tf32(acc / fmaxf(nraw, 1.f));
        __syncthreads();
    }
}

// ---------------- final projection: [1024 x 1280] @ [1024 x 1280]^T in tf32 ----------------
#define SMEM_FG ((128 * 36 + 64 * 36) * 2 * 4)

__global__ __launch_bounds__(256, 2)
void final_gemm(const float* __restrict__ bc, float* __restrict__ out) {
    extern __shared__ __align__(16) float fg[];
    float* sAq = fg;                  // [2][128*36]
    float* sBq = fg + 2 * 128 * 36;   // [2][64*36]
    const int tid = threadIdx.x, lane = tid & 31, wid = tid >> 5;
    const int wm = wid >> 1, wn = wid & 1;
    const int lbase = blockIdx.y * 128, dbase = blockIdx.x * 64;
    const int NCH = KCAT / 32;   // 40

    float acc[2][4][4];
#pragma unroll
    for (int mt = 0; mt < 2; ++mt)
#pragma unroll
        for (int nt = 0; nt < 4; ++nt)
#pragma unroll
            for (int j = 0; j < 4; ++j) acc[mt][nt][j] = 0.f;

    {
        for (int i = tid; i < 1024; i += 256) {
            int row = i >> 3, seg = i & 7;
            cp_async16(sAq + row * 36 + seg * 4, g_cat + (size_t)(lbase + row) * KCAT + seg * 4);
        }
        for (int i = tid; i < 512; i += 256) {
            int row = i >> 3, seg = i & 7;
            cp_async16(sBq + row * 36 + seg * 4, g_wct + (size_t)(dbase + row) * KCAT + seg * 4);
        }
        asm volatile("cp.async.commit_group;\n");
    }

    for (int ch = 0; ch < NCH; ++ch) {
        const int buf = ch & 1;
        if (ch + 1 < NCH) {
            const int nb = buf ^ 1;
            const size_t kb = (size_t)(ch + 1) * 32;
            for (int i = tid; i < 1024; i += 256) {
                int row = i >> 3, seg = i & 7;
                cp_async16(sAq + nb * 128 * 36 + row * 36 + seg * 4,
                           g_cat + (size_t)(lbase + row) * KCAT + kb + seg * 4);
            }
            for (int i = tid; i < 512; i += 256) {
                int row = i >> 3, seg = i & 7;
                cp_async16(sBq + nb * 64 * 36 + row * 36 + seg * 4,
                           g_wct + (size_t)(dbase + row) * KCAT + kb + seg * 4);
            }
            asm volatile("cp.async.commit_group;\n");
            asm volatile("cp.async.wait_group 1;\n");
        } else {
            asm volatile("cp.async.wait_group 0;\n");
        }
        __syncthreads();

        const float* Ab = sAq + buf * 128 * 36;
        const float* Bb = sBq + buf * 64 * 36;
#pragma unroll
        for (int ks = 0; ks < 4; ++ks) {
            const int k0 = ks * 8 + (lane & 3);
            unsigned a[2][4], b[4][2];
#pragma unroll
            for (int mt = 0; mt < 2; ++mt) {
                const int r = wm * 32 + mt * 16 + (lane >> 2);
                a[mt][0] = __float_as_uint(Ab[r * 36 + k0]);
                a[mt][1] = __float_as_uint(Ab[(r + 8) * 36 + k0]);
                a[mt][2] = __float_as_uint(Ab[r * 36 + k0 + 4]);
                a[mt][3] = __float_as_uint(Ab[(r + 8) * 36 + k0 + 4]);
            }
#pragma unroll
            for (int nt = 0; nt < 4; ++nt) {
                const int n = wn * 32 + nt * 8 + (lane >> 2);
                b[nt][0] = __float_as_uint(Bb[n * 36 + k0]);
                b[nt][1] = __float_as_uint(Bb[n * 36 + k0 + 4]);
            }
#pragma unroll
            for (int mt = 0; mt < 2; ++mt)
#pragma unroll
                for (int nt = 0; nt < 4; ++nt) mma1688_tf32(acc[mt][nt], a[mt], b[nt]);
        }
        __syncthreads();
    }

#pragma unroll
    for (int mt = 0; mt < 2; ++mt)
#pragma unroll
        for (int nt = 0; nt < 4; ++nt) {
            const int r = wm * 32 + mt * 16 + (lane >> 2);
            const int c = wn * 32 + nt * 8 + (lane & 3) * 2;
            const int gr = lbase + r, gc = dbase + c;
            const float b0 = __ldg(&bc[gc]), b1v = __ldg(&bc[gc + 1]);
            out[(size_t)gr * CS + gc]           = acc[mt][nt][0] + b0;
            out[(size_t)gr * CS + gc + 1]       = acc[mt][nt][1] + b1v;
            out[(size_t)(gr + 8) * CS + gc]     = acc[mt][nt][2] + b0;
            out[(size_t)(gr + 8) * CS + gc + 1] = acc[mt][nt][3] + b1v;
        }
}

// ---------------- launcher (main is 4th launch for ncu capture) ----------------
extern "C" void kernel_launch(void* const* d_in, const int* in_sizes, int n_in,
                              void* d_out, int out_size) {
    const float* s_z    = (const float*)d_in[0];
    const float* s_s_in = (const float*)d_in[1];
    const float* mask   = (const float*)d_in[2];
    const float* ln_g   = (const float*)d_in[3];
    const float* ln_b   = (const float*)d_in[4];
    const float* w1     = (const float*)d_in[5];
    const float* b1     = (const float*)d_in[6];
    const float* w2     = (const float*)d_in[7];
    const float* b2     = (const float*)d_in[8];
    const float* wc     = (const float*)d_in[9];
    const float* bc     = (const float*)d_in[10];
    float* out = (float*)d_out;
    (void)in_sizes; (void)n_in; (void)out_size;

    cudaFuncSetAttribute(main_kernel, cudaFuncAttributeMaxDynamicSharedMemorySize, SMEM_MAIN);
    cudaFuncSetAttribute(cat_finalize, cudaFuncAttributeMaxDynamicSharedMemorySize, SMEM_CATF);
    cudaFuncSetAttribute(final_gemm, cudaFuncAttributeMaxDynamicSharedMemorySize, SMEM_FG);

    prep_w1b1<<<CZ + 1, 128>>>(w1, b1, ln_g, ln_b);
    norm_c<<<LDIM, 256>>>(mask);
    prep_wct<<<(CS * KCAT + 255) / 256, 256>>>(wc);
    main_kernel<<<GRID_MAIN, 512, SMEM_MAIN>>>(s_z, mask);
    prep_catss<<<(LDIM * CS + 255) / 256, 256>>>(s_s_in);
    cat_finalize<<<64, 256, SMEM_CATF>>>(w2, b2);
    final_gemm<<<dim3(16, 8), 256, SMEM_FG>>>(bc, out);
}